// round 17
// baseline (speedup 1.0000x reference)
#include <cuda_runtime.h>
#include <cuda_bf16.h>
#include <cstdint>

#define DIMN 512
#define MT   64
#define NROWS 65536
#define NCTAS (NROWS / MT)        // 1024
#define NTHREADS 256
#define ETA   0.1f
#define OMETA 0.9f

// SMEM: A-tile [64][512] bf16 swizzled (64KB) + flags[2][8]
static constexpr uint32_t A_OFF  = 0;
static constexpr uint32_t FL_OFF = 65536;
static constexpr uint32_t SMEM_TOTAL = 65536 + 128;

// B-fragment image of G' = -eta*0.5*(G+G^T) (diag 0), bf16, mma.sync .col B frags:
//   u32 index = ((s*16 + wc)*32 + lane)*8 + g*2 + r
//   s = k16 step (0..31), wc = n32 col-group (0..15), g = n8 group in n32 (0..3),
//   r: k-half. reg holds {G'[k][n], G'[k+1][n]}, k = s*16 + (lane&3)*2 + r*8,
//   n = wc*32 + g*8 + (lane>>2); low bf16 = even k.
// Strides: per-s = 4096 u32 = 1024 uint4; per-wc = 256 u32 = 64 uint4.
__device__ uint32_t g_bfrag[32 * 16 * 32 * 8];   // 512KB

__global__ void lca_prep_kernel(const float* __restrict__ G) {
    int idx = blockIdx.x * blockDim.x + threadIdx.x;   // 65536
    int g  = idx & 3;
    int l  = (idx >> 2) & 31;
    int wc = (idx >> 7) & 15;
    int s  = idx >> 11;
    int n  = wc * 32 + g * 8 + (l >> 2);
    int k0 = s * 16 + (l & 3) * 2;
    float v00 = (k0     == n) ? 0.0f : -0.05f * (G[(k0    ) * DIMN + n] + G[n * DIMN + (k0    )]);
    float v01 = (k0 + 1 == n) ? 0.0f : -0.05f * (G[(k0 + 1) * DIMN + n] + G[n * DIMN + (k0 + 1)]);
    float v10 = (k0 + 8 == n) ? 0.0f : -0.05f * (G[(k0 + 8) * DIMN + n] + G[n * DIMN + (k0 + 8)]);
    float v11 = (k0 + 9 == n) ? 0.0f : -0.05f * (G[(k0 + 9) * DIMN + n] + G[n * DIMN + (k0 + 9)]);
    __nv_bfloat162 p0 = __floats2bfloat162_rn(v00, v01);
    __nv_bfloat162 p1 = __floats2bfloat162_rn(v10, v11);
    uint32_t* dst = g_bfrag + ((((size_t)s * 16 + wc) * 32 + l) * 8 + g * 2);
    dst[0] = *reinterpret_cast<uint32_t*>(&p0);
    dst[1] = *reinterpret_cast<uint32_t*>(&p1);
}

__device__ __forceinline__ uint32_t smem_u32(const void* p) {
    uint32_t a;
    asm("{ .reg .u64 t; cvta.to.shared.u64 t, %1; cvt.u32.u64 %0, t; }" : "=r"(a) : "l"(p));
    return a;
}
__device__ __forceinline__ void ldsm4(uint32_t* r, uint32_t addr) {
    asm volatile("ldmatrix.sync.aligned.m8n8.x4.shared.b16 {%0,%1,%2,%3}, [%4];"
                 : "=r"(r[0]), "=r"(r[1]), "=r"(r[2]), "=r"(r[3]) : "r"(addr));
}
__device__ __forceinline__ void mma_bf16(float* c, const uint32_t* a, uint32_t b0, uint32_t b1) {
    asm volatile("mma.sync.aligned.m16n8k16.row.col.f32.bf16.bf16.f32 "
                 "{%0,%1,%2,%3}, {%4,%5,%6,%7}, {%8,%9}, {%0,%1,%2,%3};"
                 : "+f"(c[0]), "+f"(c[1]), "+f"(c[2]), "+f"(c[3])
                 : "r"(a[0]), "r"(a[1]), "r"(a[2]), "r"(a[3]), "r"(b0), "r"(b1));
}

__global__ __launch_bounds__(NTHREADS, 1)
void lca_main_kernel(const float* __restrict__ u,
                     const float* __restrict__ log_lam,
                     float* __restrict__ out) {
    extern __shared__ char smem[];
    const uint32_t sb = smem_u32(smem);
    uint32_t* flagsm = reinterpret_cast<uint32_t*>(smem + FL_OFF);   // [2][8]
    const int tid  = threadIdx.x;
    const int lane = tid & 31;
    const int wn   = tid >> 5;             // warp 0..7 owns n cols wn*64..+63, ALL 64 rows
    const int n0   = wn * 64;
    const int grow0 = blockIdx.x * MT;
    const float lam = expf(log_lam[0]);
    const int r4 = lane >> 2;
    const int c2 = (lane & 3) * 2;

    float acc[4][8][4];                    // [m16 grp][n8 grp][quad] = 128 regs

    // A-operand ldsm addressing (proven): row-group q at a_l0 + q*16384 + swizzled k-offset
    const uint32_t a_l0 = sb + A_OFF + (uint32_t)(lane & 15) * 1024u;
    const uint32_t a_cbs = ((uint32_t)(lane >> 4)) ^ ((uint32_t)(lane & 7));
    // B-frag base: slice wc = 2*wn (this warp's first n32 group); +64 uint4 = next slice
    const uint4* bw = reinterpret_cast<const uint4*>(
        g_bfrag + (((size_t)(2 * wn)) * 32 + (size_t)lane) * 8);
    // per k16 step: +1024 uint4

    // ---- init: v1 = eta*u; a1 = soft(v1) -> SMEM + flags slot0; acc = 0.9*v1 + 0.1*u ----
    {
        bool nzw = false;
#pragma unroll
        for (int fm = 0; fm < 4; fm++)
#pragma unroll
        for (int rh = 0; rh < 2; rh++) {
            int rl = fm * 16 + rh * 8 + r4;
            const float* urow = u + (size_t)(grow0 + rl) * DIMN;
            uint32_t abase = sb + A_OFF + (uint32_t)rl * 1024u + (uint32_t)(c2 * 2);
            uint32_t sw = (uint32_t)(rl & 7);
#pragma unroll
            for (int ni = 0; ni < 8; ni++) {
                float2 uv = *(const float2*)(urow + n0 + ni * 8 + c2);
                float v0 = ETA * uv.x, v1 = ETA * uv.y;
                float s0 = fabsf(v0) - lam, s1 = fabsf(v1) - lam;
                float a0 = (s0 > 0.0f) ? copysignf(s0, v0) : 0.0f;
                float a1 = (s1 > 0.0f) ? copysignf(s1, v1) : 0.0f;
                nzw |= (a0 != 0.0f) || (a1 != 0.0f);
                __nv_bfloat162 h2 = __floats2bfloat162_rn(a0, a1);
                uint32_t unit = (uint32_t)(wn * 8 + ni);
                uint32_t aaddr = abase + ((unit ^ sw) << 4);
                asm volatile("st.shared.b32 [%0], %1;" :: "r"(aaddr), "r"(*(uint32_t*)&h2) : "memory");
                acc[fm][ni][rh * 2 + 0] = fmaf(OMETA, v0, ETA * uv.x);
                acc[fm][ni][rh * 2 + 1] = fmaf(OMETA, v1, ETA * uv.y);
            }
        }
        bool w = __any_sync(0xFFFFFFFFu, nzw);
        if (lane == 0) flagsm[wn] = w ? 1u : 0u;   // sole writer of flag[.][wn]
    }
    __syncthreads();   // A-tile + flags slot0 visible

    // ---- 9 iterations; no barriers inside the k loop (B never touches SMEM) ----
#pragma unroll 1
    for (int it = 0; it < 9; it++) {
        const int slot = it & 1;
#pragma unroll 1
        for (int kb = 0; kb < 8; kb++) {          // k-chunk kb: steps 4kb..4kb+3
            if (!flagsm[slot * 8 + kb]) continue;
            const int s0 = kb * 4;
            const uint4* bp = bw + (size_t)s0 * 1024;
            uint4 B0 = __ldg(bp);         // slice 2wn  (ni 0..3)
            uint4 B1 = __ldg(bp + 1);
            uint4 B2 = __ldg(bp + 64);    // slice 2wn+1 (ni 4..7)
            uint4 B3 = __ldg(bp + 65);
#pragma unroll
            for (int h = 0; h < 4; h++) {
                const int s = s0 + h;
                uint32_t aoff = (((uint32_t)(s << 1) ^ a_cbs) << 4);
                uint32_t Af[4][4];
                ldsm4(Af[0], a_l0 + aoff);
                ldsm4(Af[1], a_l0 + 16384u + aoff);
                ldsm4(Af[2], a_l0 + 32768u + aoff);
                ldsm4(Af[3], a_l0 + 49152u + aoff);
                uint4 N0, N1, N2, N3;
                if (h < 3) {
                    const uint4* bn = bw + (size_t)(s + 1) * 1024;
                    N0 = __ldg(bn); N1 = __ldg(bn + 1);
                    N2 = __ldg(bn + 64); N3 = __ldg(bn + 65);
                }
#pragma unroll
                for (int q = 0; q < 4; q++) {
                    mma_bf16(acc[q][0], Af[q], B0.x, B0.y);
                    mma_bf16(acc[q][1], Af[q], B0.z, B0.w);
                    mma_bf16(acc[q][2], Af[q], B1.x, B1.y);
                    mma_bf16(acc[q][3], Af[q], B1.z, B1.w);
                    mma_bf16(acc[q][4], Af[q], B2.x, B2.y);
                    mma_bf16(acc[q][5], Af[q], B2.z, B2.w);
                    mma_bf16(acc[q][6], Af[q], B3.x, B3.y);
                    mma_bf16(acc[q][7], Af[q], B3.z, B3.w);
                }
                if (h < 3) { B0 = N0; B1 = N1; B2 = N2; B3 = N3; }
            }
        }
        __syncthreads();   // all warps' MMAs done before A-tile rewrite

        if (it < 8) {
            bool nzw = false;
            const int wslot = slot ^ 1;
#pragma unroll
            for (int fm = 0; fm < 4; fm++)
#pragma unroll
            for (int rh = 0; rh < 2; rh++) {
                int rl = fm * 16 + rh * 8 + r4;
                const float* urow = u + (size_t)(grow0 + rl) * DIMN;
                uint32_t abase = sb + A_OFF + (uint32_t)rl * 1024u + (uint32_t)(c2 * 2);
                uint32_t sw = (uint32_t)(rl & 7);
#pragma unroll
                for (int ni = 0; ni < 8; ni++) {
                    float v0 = acc[fm][ni][rh * 2 + 0];
                    float v1 = acc[fm][ni][rh * 2 + 1];
                    float s0 = fabsf(v0) - lam, s1 = fabsf(v1) - lam;
                    float a0 = (s0 > 0.0f) ? copysignf(s0, v0) : 0.0f;
                    float a1 = (s1 > 0.0f) ? copysignf(s1, v1) : 0.0f;
                    nzw |= (a0 != 0.0f) || (a1 != 0.0f);
                    __nv_bfloat162 h2 = __floats2bfloat162_rn(a0, a1);
                    uint32_t unit = (uint32_t)(wn * 8 + ni);
                    uint32_t aaddr = abase + ((unit ^ sw) << 4);
                    asm volatile("st.shared.b32 [%0], %1;" :: "r"(aaddr), "r"(*(uint32_t*)&h2) : "memory");
                    float2 uv = *(const float2*)(urow + n0 + ni * 8 + c2);
                    acc[fm][ni][rh * 2 + 0] = fmaf(OMETA, v0, ETA * uv.x);
                    acc[fm][ni][rh * 2 + 1] = fmaf(OMETA, v1, ETA * uv.y);
                }
            }
            bool w = __any_sync(0xFFFFFFFFu, nzw);
            if (lane == 0) flagsm[wslot * 8 + wn] = w ? 1u : 0u;
            __syncthreads();   // a_{t+1} + flags visible before next iteration
        } else {
            // final: a10 = soft(v10) -> out
#pragma unroll
            for (int fm = 0; fm < 4; fm++)
#pragma unroll
            for (int rh = 0; rh < 2; rh++) {
                int rl = fm * 16 + rh * 8 + r4;
                float* orow = out + (size_t)(grow0 + rl) * DIMN;
#pragma unroll
                for (int ni = 0; ni < 8; ni++) {
                    float v0 = acc[fm][ni][rh * 2 + 0];
                    float v1 = acc[fm][ni][rh * 2 + 1];
                    float s0 = fabsf(v0) - lam, s1 = fabsf(v1) - lam;
                    float2 o;
                    o.x = (s0 > 0.0f) ? copysignf(s0, v0) : 0.0f;
                    o.y = (s1 > 0.0f) ? copysignf(s1, v1) : 0.0f;
                    *(float2*)(orow + n0 + ni * 8 + c2) = o;
                }
            }
        }
    }
}

extern "C" void kernel_launch(void* const* d_in, const int* in_sizes, int n_in,
                              void* d_out, int out_size) {
    const float* u = nullptr;
    const float* G = nullptr;
    const float* ll = nullptr;
    for (int i = 0; i < n_in; i++) {
        if (in_sizes[i] == NROWS * DIMN)      u  = (const float*)d_in[i];
        else if (in_sizes[i] == DIMN * DIMN)  G  = (const float*)d_in[i];
        else                                  ll = (const float*)d_in[i];
    }
    float* out = (float*)d_out;

    lca_prep_kernel<<<128, 512>>>(G);

    cudaFuncSetAttribute(lca_main_kernel,
                         cudaFuncAttributeMaxDynamicSharedMemorySize, SMEM_TOTAL);
    lca_main_kernel<<<NCTAS, NTHREADS, SMEM_TOTAL>>>(u, ll, out);
}